// round 8
// baseline (speedup 1.0000x reference)
#include <cuda_runtime.h>
#include <cuda_bf16.h>
#include <cstdint>

#define C_DIM 1024
#define C3    3072
#define BB    2
#define TT    2048
#define HH    16
#define MTOT  4096   // BB*TT

// ---------------------------------------------------------------------------
// Scratch buffers (__device__ globals: the sanctioned no-alloc workaround)
// ---------------------------------------------------------------------------
__device__ __nv_bfloat16 g_qkvh[(size_t)MTOT * C3];     // QKV split hi (Q pre-scaled)
__device__ __nv_bfloat16 g_qkvl[(size_t)MTOT * C3];     // QKV split lo
__device__ __nv_bfloat16 g_xhi[(size_t)MTOT * C_DIM];
__device__ __nv_bfloat16 g_xlo[(size_t)MTOT * C_DIM];
__device__ __nv_bfloat16 g_ahi[(size_t)MTOT * C_DIM];   // attn out hi (K-major)
__device__ __nv_bfloat16 g_alo[(size_t)MTOT * C_DIM];   // attn out lo
__device__ __nv_bfloat16 g_wqt_hi[(size_t)C3 * C_DIM];  // qkv_w^T [N=3072][K=1024]
__device__ __nv_bfloat16 g_wqt_lo[(size_t)C3 * C_DIM];
__device__ __nv_bfloat16 g_wot_hi[(size_t)C_DIM * C_DIM];
__device__ __nv_bfloat16 g_wot_lo[(size_t)C_DIM * C_DIM];

// ---------------------------------------------------------------------------
// Portable tensor-core helpers (compute_103-safe: ldmatrix / mma.sync / cp.async)
// ---------------------------------------------------------------------------
__device__ __forceinline__ uint32_t smem_u32(const void* p) {
    uint32_t a;
    asm("{ .reg .u64 t; cvta.to.shared.u64 t, %1; cvt.u32.u64 %0, t; }"
        : "=r"(a) : "l"(p));
    return a;
}
#define SWZ128(off) ((off) ^ (((off) >> 3) & 0x70))

__device__ __forceinline__ void ldsm4(uint32_t* r, uint32_t addr) {
    asm volatile("ldmatrix.sync.aligned.m8n8.x4.shared.b16 {%0,%1,%2,%3}, [%4];"
        : "=r"(r[0]), "=r"(r[1]), "=r"(r[2]), "=r"(r[3]) : "r"(addr));
}
__device__ __forceinline__ void ldsm4t(uint32_t* r, uint32_t addr) {
    asm volatile("ldmatrix.sync.aligned.m8n8.x4.trans.shared.b16 {%0,%1,%2,%3}, [%4];"
        : "=r"(r[0]), "=r"(r[1]), "=r"(r[2]), "=r"(r[3]) : "r"(addr));
}
__device__ __forceinline__ void mma_bf16(float* d, const uint32_t* a, const uint32_t* b) {
    asm volatile("mma.sync.aligned.m16n8k16.row.col.f32.bf16.bf16.f32 "
        "{%0,%1,%2,%3}, {%4,%5,%6,%7}, {%8,%9}, {%0,%1,%2,%3};"
        : "+f"(d[0]), "+f"(d[1]), "+f"(d[2]), "+f"(d[3])
        : "r"(a[0]), "r"(a[1]), "r"(a[2]), "r"(a[3]), "r"(b[0]), "r"(b[1]));
}
#define CP16(dst, src)  asm volatile("cp.async.cg.shared.global [%0], [%1], 16;" :: "r"(dst), "l"(src) : "memory")
#define CP_COMMIT()     asm volatile("cp.async.commit_group;" ::: "memory")
#define CP_WAIT0()      asm volatile("cp.async.wait_group 0;" ::: "memory")
#define CP_WAIT1()      asm volatile("cp.async.wait_group 1;" ::: "memory")

__device__ __forceinline__ uint32_t pack_bf16(float a, float b) {
    __nv_bfloat162 p;
    p.x = __float2bfloat16(a);
    p.y = __float2bfloat16(b);
    return *(uint32_t*)&p;
}

// ---------------------------------------------------------------------------
// Prepass: fp32 -> (hi, lo) bf16 split.  n4 = element_count/4.
// ---------------------------------------------------------------------------
__global__ __launch_bounds__(256) void split_k(const float* __restrict__ in,
    __nv_bfloat16* __restrict__ hi, __nv_bfloat16* __restrict__ lo, int n4)
{
    const int i = blockIdx.x * 256 + threadIdx.x;
    if (i >= n4) return;
    const float4 v = ((const float4*)in)[i];
    __nv_bfloat16 h0 = __float2bfloat16(v.x), h1 = __float2bfloat16(v.y);
    __nv_bfloat16 h2 = __float2bfloat16(v.z), h3 = __float2bfloat16(v.w);
    __nv_bfloat162 hp0, hp1, lp0, lp1;
    hp0.x = h0; hp0.y = h1; hp1.x = h2; hp1.y = h3;
    lp0.x = __float2bfloat16(v.x - __bfloat162float(h0));
    lp0.y = __float2bfloat16(v.y - __bfloat162float(h1));
    lp1.x = __float2bfloat16(v.z - __bfloat162float(h2));
    lp1.y = __float2bfloat16(v.w - __bfloat162float(h3));
    ((__nv_bfloat162*)hi)[i * 2 + 0] = hp0;
    ((__nv_bfloat162*)hi)[i * 2 + 1] = hp1;
    ((__nv_bfloat162*)lo)[i * 2 + 0] = lp0;
    ((__nv_bfloat162*)lo)[i * 2 + 1] = lp1;
}

// ---------------------------------------------------------------------------
// Prepass: transpose + split.  in [K][N] fp32 -> out hi/lo [N][K] bf16.
// ---------------------------------------------------------------------------
__global__ __launch_bounds__(256) void tsplit_k(const float* __restrict__ in,
    __nv_bfloat16* __restrict__ hiT, __nv_bfloat16* __restrict__ loT, int K, int N)
{
    __shared__ float tile[32][33];
    const int n0 = blockIdx.x * 32, k0 = blockIdx.y * 32;
    const int tx = threadIdx.x, ty = threadIdx.y;
    for (int i = ty; i < 32; i += 8)
        tile[i][tx] = in[(size_t)(k0 + i) * N + n0 + tx];
    __syncthreads();
    for (int i = ty; i < 32; i += 8) {
        const float v = tile[tx][i];
        const __nv_bfloat16 h = __float2bfloat16(v);
        hiT[(size_t)(n0 + i) * K + k0 + tx] = h;
        loT[(size_t)(n0 + i) * K + k0 + tx] = __float2bfloat16(v - __bfloat162float(h));
    }
}

// ---------------------------------------------------------------------------
// mma.sync GEMM v4: C[256x128 per CTA] = A @ B^T + bias.
// Warp tile 64x64 (4M x 2N warps). B fragments pipelined per-ni (8 live regs,
// double-buffered) to stay under the register cap; A frags 32 regs; acc 128.
// BK=64, 2-stage cp.async pipeline; smem 2 x 96KB = 192KB; 1 CTA/SM.
// mode 0: fp32 out.  mode 1: hi/lo bf16 split out, Q block pre-scaled 0.125.
// ---------------------------------------------------------------------------
#define GA_B      32768                  // one A array (256 x 128B)
#define GB_B      16384                  // one B array (128 x 128B)
#define GSTAGE_B  (2 * GA_B + 2 * GB_B)  // 98304
#define SMEM_GEMM (2 * GSTAGE_B)         // 196608

__global__ __launch_bounds__(256, 1) void gemm_mma(
    const __nv_bfloat16* __restrict__ Ahi, const __nv_bfloat16* __restrict__ Alo,
    const __nv_bfloat16* __restrict__ Bhi, const __nv_bfloat16* __restrict__ Blo,
    const float* __restrict__ bias, float* __restrict__ Cf,
    __nv_bfloat16* __restrict__ Chi, __nv_bfloat16* __restrict__ Clo,
    int Ntot, int mode)
{
    extern __shared__ __align__(1024) char smg[];
    const uint32_t sb = smem_u32(smg);
    const int t = threadIdx.x, w = t >> 5, lane = t & 31;
    const int m0 = blockIdx.y << 8, n0 = blockIdx.x << 7;
    const int wm = (w >> 1) << 6, wn = (w & 1) << 6;

    const __nv_bfloat16* srcA[2] = { Ahi + (size_t)m0 * 1024, Alo + (size_t)m0 * 1024 };
    const __nv_bfloat16* srcB[2] = { Bhi + (size_t)n0 * 1024, Blo + (size_t)n0 * 1024 };

    float acc[4][8][4];
#pragma unroll
    for (int i = 0; i < 4; i++)
#pragma unroll
        for (int j = 0; j < 8; j++)
#pragma unroll
            for (int q = 0; q < 4; q++) acc[i][j][q] = 0.f;

    auto fill = [&](int c, int stg) {
        const int k0 = c << 6;
        const uint32_t stb = sb + stg * GSTAGE_B;
#pragma unroll
        for (int arr = 0; arr < 2; ++arr) {          // A hi/lo: 256 rows
            const uint32_t db = stb + arr * GA_B;
            const __nv_bfloat16* s = srcA[arr] + k0;
#pragma unroll
            for (int i = 0; i < 8; ++i) {
                const int idx = t + (i << 8);        // 0..2047
                const int row = idx >> 3, seg = idx & 7;
                CP16(db + SWZ128(row * 128 + seg * 16),
                     s + (size_t)row * 1024 + seg * 8);
            }
        }
#pragma unroll
        for (int arr = 0; arr < 2; ++arr) {          // B hi/lo: 128 rows
            const uint32_t db = stb + 2 * GA_B + arr * GB_B;
            const __nv_bfloat16* s = srcB[arr] + k0;
#pragma unroll
            for (int i = 0; i < 4; ++i) {
                const int idx = t + (i << 8);        // 0..1023
                const int row = idx >> 3, seg = idx & 7;
                CP16(db + SWZ128(row * 128 + seg * 16),
                     s + (size_t)row * 1024 + seg * 8);
            }
        }
    };

    fill(0, 0);
    CP_COMMIT();
    CP_WAIT0();
    __syncthreads();

    const int aRow = wm + (lane & 15);
    const int bRow = wn + ((lane >> 4) << 3) + (lane & 7);

    for (int c = 0; c < 16; ++c) {
        const int stg = c & 1;
        if (c < 15) { fill(c + 1, stg ^ 1); CP_COMMIT(); }

        const uint32_t stA_h = sb + stg * GSTAGE_B;
        const uint32_t stA_l = stA_h + GA_B;
        const uint32_t stB_h = stA_h + 2 * GA_B;
        const uint32_t stB_l = stB_h + GB_B;

#pragma unroll
        for (int k16 = 0; k16 < 4; ++k16) {
            const int kbA = k16 * 32 + ((lane >> 4) & 1) * 16;
            const int kbB = k16 * 32 + ((lane >> 3) & 1) * 16;

            uint32_t aH[4][4], aL[4][4];
#pragma unroll
            for (int mi = 0; mi < 4; ++mi) {
                const uint32_t off = SWZ128((aRow + mi * 16) * 128 + kbA);
                ldsm4(aH[mi], stA_h + off);
                ldsm4(aL[mi], stA_l + off);
            }
            // B fragments: double-buffered per-ni (8 live regs + prefetch)
            uint32_t bH[2][4], bL[2][4];
            {
                const uint32_t off = SWZ128(bRow * 128 + kbB);
                ldsm4(bH[0], stB_h + off);
                ldsm4(bL[0], stB_l + off);
            }
#pragma unroll
            for (int ni = 0; ni < 4; ++ni) {
                const int cur = ni & 1;
                if (ni < 3) {
                    const uint32_t off = SWZ128((bRow + (ni + 1) * 16) * 128 + kbB);
                    ldsm4(bH[cur ^ 1], stB_h + off);
                    ldsm4(bL[cur ^ 1], stB_l + off);
                }
#pragma unroll
                for (int mi = 0; mi < 4; ++mi)
#pragma unroll
                    for (int h2 = 0; h2 < 2; ++h2) {
                        float* d = acc[mi][ni * 2 + h2];
                        mma_bf16(d, aH[mi], &bH[cur][h2 * 2]);
                        mma_bf16(d, aH[mi], &bL[cur][h2 * 2]);
                        mma_bf16(d, aL[mi], &bH[cur][h2 * 2]);
                    }
            }
        }
        CP_WAIT0();
        __syncthreads();
    }

    const int g2 = lane >> 2, tg = lane & 3;
    if (mode == 0) {
#pragma unroll
        for (int mi = 0; mi < 4; ++mi) {
            const int row0 = m0 + wm + mi * 16 + g2;
#pragma unroll
            for (int j = 0; j < 8; ++j) {
                const int col = n0 + wn + j * 8 + tg * 2;
                const float2 b2 = *(const float2*)&bias[col];
                const float* d = acc[mi][j];
                float2 lo2 = { d[0] + b2.x, d[1] + b2.y };
                float2 hi2 = { d[2] + b2.x, d[3] + b2.y };
                *(float2*)&Cf[(size_t)row0 * Ntot + col] = lo2;
                *(float2*)&Cf[(size_t)(row0 + 8) * Ntot + col] = hi2;
            }
        }
    } else {
        const float scale = (n0 < C_DIM) ? 0.125f : 1.0f;   // Q block pre-scale
#pragma unroll
        for (int mi = 0; mi < 4; ++mi) {
            const int row0 = m0 + wm + mi * 16 + g2;
#pragma unroll
            for (int j = 0; j < 8; ++j) {
                const int col = n0 + wn + j * 8 + tg * 2;
                const float2 b2 = *(const float2*)&bias[col];
                const float* d = acc[mi][j];
                const float v0 = (d[0] + b2.x) * scale, v1 = (d[1] + b2.y) * scale;
                const float v2 = (d[2] + b2.x) * scale, v3 = (d[3] + b2.y) * scale;
                const float e0 = __bfloat162float(__float2bfloat16(v0));
                const float e1 = __bfloat162float(__float2bfloat16(v1));
                const float e2 = __bfloat162float(__float2bfloat16(v2));
                const float e3 = __bfloat162float(__float2bfloat16(v3));
                const size_t o0 = (size_t)row0 * Ntot + col;
                const size_t o1 = (size_t)(row0 + 8) * Ntot + col;
                *(uint32_t*)&Chi[o0] = pack_bf16(v0, v1);
                *(uint32_t*)&Clo[o0] = pack_bf16(v0 - e0, v1 - e1);
                *(uint32_t*)&Chi[o1] = pack_bf16(v2, v3);
                *(uint32_t*)&Clo[o1] = pack_bf16(v2 - e2, v3 - e3);
            }
        }
    }
}

// ---------------------------------------------------------------------------
// Flash attention v3: CTA = 256 queries x one (b,h); 8 warps x 32 rows.
// K/V fragments amortized over 2x query rows vs v2; key tiles of 64.
// Smem: Qh,Ql[256][64] (64KB) + 2 stages x {Kh,Kl,Vh,Vl}[64][64] (64KB) = 128KB.
// ---------------------------------------------------------------------------
#define SMEM_ATT2 131072

__global__ __launch_bounds__(256) void attn_mma(
    const __nv_bfloat16* __restrict__ qh, const __nv_bfloat16* __restrict__ ql,
    __nv_bfloat16* __restrict__ ohi, __nv_bfloat16* __restrict__ olo)
{
    extern __shared__ __align__(1024) char sma[];
    const uint32_t sb  = smem_u32(sma);
    const uint32_t sQh = sb, sQl = sb + 32768;

    const int t = threadIdx.x, w = t >> 5, lane = t & 31;
    const int g = lane >> 2, tq = lane & 3;
    const int qi = gridDim.x - 1 - blockIdx.x;      // heavy tiles first
    const int bh = blockIdx.y, b = bh >> 4, h = bh & 15;
    const int qbase = qi << 8;                      // 256-query block
    const size_t brow = (size_t)b * TT;
    const int wm = w << 5;                          // 32 rows per warp
    const int hcol = h * 64;

    auto fillQ = [&]() {
#pragma unroll
        for (int i = 0; i < 16; ++i) {
            const int idx = t + (i << 8);            // 0..4095
            const int arr = idx >> 11;               // 0 hi, 1 lo
            const int r = (idx >> 3) & 255, seg = idx & 7;
            const __nv_bfloat16* src =
                (arr ? ql : qh) + (brow + qbase + r) * C3 + hcol + seg * 8;
            CP16((arr ? sQl : sQh) + SWZ128(r * 128 + seg * 16), src);
        }
    };
    auto fillKV = [&](int kt, int buf) {
        const int kb = kt << 6;
        const uint32_t sbase = sb + 65536 + buf * 32768;
#pragma unroll
        for (int i = 0; i < 8; ++i) {
            const int idx = t + (i << 8);            // 0..2047
            const int arr = idx >> 9;                // 0 Kh, 1 Kl, 2 Vh, 3 Vl
            const int r = (idx >> 3) & 63, seg = idx & 7;
            const int colbase = ((arr < 2) ? C_DIM : 2 * C_DIM) + hcol;
            const __nv_bfloat16* src =
                ((arr & 1) ? ql : qh) + (brow + kb + r) * C3 + colbase + seg * 8;
            CP16(sbase + arr * 8192 + SWZ128(r * 128 + seg * 16), src);
        }
    };

    float oacc[2][8][4];
#pragma unroll
    for (int mi = 0; mi < 2; ++mi)
#pragma unroll
        for (int j = 0; j < 8; ++j)
#pragma unroll
            for (int q = 0; q < 4; ++q) oacc[mi][j][q] = 0.f;
    float mrow[4] = { -1e30f, -1e30f, -1e30f, -1e30f };
    float lrow[4] = { 0.f, 0.f, 0.f, 0.f };

    const int aRow  = wm + (lane & 15);
    const int bRowS = ((lane >> 4) << 3) + (lane & 7);
    const int ntiles = 4 * qi + 4;

    uint32_t aQh[4][2][4], aQl[4][2][4];             // [k16][mi][4]

    fillQ();
    fillKV(0, 0);
    CP_COMMIT();

    for (int kt = 0; kt < ntiles; ++kt) {
        const int kb = kt << 6;
        const uint32_t sKh = sb + 65536 + (kt & 1) * 32768;
        const uint32_t sKl = sKh + 8192, sVh = sKh + 16384, sVl = sKh + 24576;

        if (kt + 1 < ntiles) {
            fillKV(kt + 1, (kt + 1) & 1);
            CP_COMMIT();
            CP_WAIT1();
        } else {
            CP_WAIT0();
        }
        __syncthreads();

        if (kt == 0) {
#pragma unroll
            for (int k16 = 0; k16 < 4; ++k16) {
                const int kbA = k16 * 32 + ((lane >> 4) & 1) * 16;
#pragma unroll
                for (int mi = 0; mi < 2; ++mi) {
                    const uint32_t offA = SWZ128((aRow + mi * 16) * 128 + kbA);
                    ldsm4(aQh[k16][mi], sQh + offA);
                    ldsm4(aQl[k16][mi], sQl + offA);
                }
            }
        }

        // ---- S = Q K^T (split, fp32 accum), 32 rows x 64 keys per warp ----
        float sacc[2][8][4];
#pragma unroll
        for (int mi = 0; mi < 2; ++mi)
#pragma unroll
            for (int j = 0; j < 8; ++j)
#pragma unroll
                for (int q = 0; q < 4; ++q) sacc[mi][j][q] = 0.f;

#pragma unroll
        for (int k16 = 0; k16 < 4; ++k16) {
            const int kbB = k16 * 32 + ((lane >> 3) & 1) * 16;
            uint32_t bH[2][4], bL[2][4];
            {
                const uint32_t off = SWZ128(bRowS * 128 + kbB);
                ldsm4(bH[0], sKh + off);
                ldsm4(bL[0], sKl + off);
            }
#pragma unroll
            for (int ni = 0; ni < 4; ++ni) {
                const int cur = ni & 1;
                if (ni < 3) {
                    const uint32_t off = SWZ128((bRowS + (ni + 1) * 16) * 128 + kbB);
                    ldsm4(bH[cur ^ 1], sKh + off);
                    ldsm4(bL[cur ^ 1], sKl + off);
                }
#pragma unroll
                for (int mi = 0; mi < 2; ++mi)
#pragma unroll
                    for (int h2 = 0; h2 < 2; ++h2) {
                        float* d = sacc[mi][ni * 2 + h2];
                        mma_bf16(d, aQh[k16][mi], &bH[cur][h2 * 2]);
                        mma_bf16(d, aQh[k16][mi], &bL[cur][h2 * 2]);
                        mma_bf16(d, aQl[k16][mi], &bH[cur][h2 * 2]);
                    }
            }
        }

        // ---- causal mask (tiles overlapping the 256-query diagonal band) ----
        if (kt >= 4 * qi) {
#pragma unroll
            for (int mi = 0; mi < 2; ++mi) {
                const int row0 = qbase + wm + mi * 16 + g;
#pragma unroll
                for (int j = 0; j < 8; ++j) {
                    const int col = kb + j * 8 + tq * 2;
                    float* s = sacc[mi][j];
                    if (col     > row0)     s[0] = -1e30f;
                    if (col + 1 > row0)     s[1] = -1e30f;
                    if (col     > row0 + 8) s[2] = -1e30f;
                    if (col + 1 > row0 + 8) s[3] = -1e30f;
                }
            }
        }

        // ---- online softmax (4 row-groups/thread, quad reductions) ----
#pragma unroll
        for (int mi = 0; mi < 2; ++mi)
#pragma unroll
            for (int rr = 0; rr < 2; ++rr) {
                const int rg = mi * 2 + rr;
                const int i0 = rr * 2;
                float mt = -1e30f;
#pragma unroll
                for (int j = 0; j < 8; ++j)
                    mt = fmaxf(mt, fmaxf(sacc[mi][j][i0], sacc[mi][j][i0 + 1]));
                mt = fmaxf(mt, __shfl_xor_sync(0xffffffffu, mt, 1));
                mt = fmaxf(mt, __shfl_xor_sync(0xffffffffu, mt, 2));
                const float mn = fmaxf(mrow[rg], mt);
                const float alpha = __expf(mrow[rg] - mn);
                mrow[rg] = mn;
                float ps = 0.f;
#pragma unroll
                for (int j = 0; j < 8; ++j) {
                    const float p0 = __expf(sacc[mi][j][i0] - mn);
                    const float p1 = __expf(sacc[mi][j][i0 + 1] - mn);
                    sacc[mi][j][i0] = p0; sacc[mi][j][i0 + 1] = p1;
                    ps += p0 + p1;
                }
                ps += __shfl_xor_sync(0xffffffffu, ps, 1);
                ps += __shfl_xor_sync(0xffffffffu, ps, 2);
                lrow[rg] = lrow[rg] * alpha + ps;
#pragma unroll
                for (int j = 0; j < 8; ++j) {
                    oacc[mi][j][i0] *= alpha;
                    oacc[mi][j][i0 + 1] *= alpha;
                }
            }

        // ---- O += P V (P split register-direct; V via ldmatrix.trans) ----
#pragma unroll
        for (int kk = 0; kk < 4; ++kk) {
            uint32_t aPh[2][4], aPl[2][4];
#pragma unroll
            for (int mi = 0; mi < 2; ++mi) {
                const float* s0 = sacc[mi][2 * kk];
                const float* s1 = sacc[mi][2 * kk + 1];
                float h00 = __bfloat162float(__float2bfloat16(s0[0]));
                float h01 = __bfloat162float(__float2bfloat16(s0[1]));
                float h02 = __bfloat162float(__float2bfloat16(s0[2]));
                float h03 = __bfloat162float(__float2bfloat16(s0[3]));
                float h10 = __bfloat162float(__float2bfloat16(s1[0]));
                float h11 = __bfloat162float(__float2bfloat16(s1[1]));
                float h12 = __bfloat162float(__float2bfloat16(s1[2]));
                float h13 = __bfloat162float(__float2bfloat16(s1[3]));
                aPh[mi][0] = pack_bf16(s0[0], s0[1]);
                aPh[mi][1] = pack_bf16(s0[2], s0[3]);
                aPh[mi][2] = pack_bf16(s1[0], s1[1]);
                aPh[mi][3] = pack_bf16(s1[2], s1[3]);
                aPl[mi][0] = pack_bf16(s0[0] - h00, s0[1] - h01);
                aPl[mi][1] = pack_bf16(s0[2] - h02, s0[3] - h03);
                aPl[mi][2] = pack_bf16(s1[0] - h10, s1[1] - h11);
                aPl[mi][3] = pack_bf16(s1[2] - h12, s1[3] - h13);
            }
            const int vr = kk * 16 + (lane & 15);
            const int vc = ((lane >> 4) & 1) * 16;
#pragma unroll
            for (int ni = 0; ni < 4; ++ni) {
                uint32_t vH[4], vL[4];
                const uint32_t off = SWZ128(vr * 128 + ni * 32 + vc);
                ldsm4t(vH, sVh + off);
                ldsm4t(vL, sVl + off);
#pragma unroll
                for (int mi = 0; mi < 2; ++mi)
#pragma unroll
                    for (int h2 = 0; h2 < 2; ++h2) {
                        float* d = oacc[mi][ni * 2 + h2];
                        mma_bf16(d, aPh[mi], &vH[h2 * 2]);
                        mma_bf16(d, aPh[mi], &vL[h2 * 2]);
                        mma_bf16(d, aPl[mi], &vH[h2 * 2]);
                    }
            }
        }
        __syncthreads();
    }

    // ---- epilogue: normalize, split hi/lo, store (K-major [M][1024]) ----
#pragma unroll
    for (int mi = 0; mi < 2; ++mi) {
        const float inv0 = 1.f / lrow[mi * 2 + 0];
        const float inv1 = 1.f / lrow[mi * 2 + 1];
        const int row0 = qbase + wm + mi * 16 + g;
#pragma unroll
        for (int j = 0; j < 8; ++j) {
            const int col = hcol + j * 8 + tq * 2;
            const float v0 = oacc[mi][j][0] * inv0, v1 = oacc[mi][j][1] * inv0;
            const float v2 = oacc[mi][j][2] * inv1, v3 = oacc[mi][j][3] * inv1;
            const float e0 = __bfloat162float(__float2bfloat16(v0));
            const float e1 = __bfloat162float(__float2bfloat16(v1));
            const float e2 = __bfloat162float(__float2bfloat16(v2));
            const float e3 = __bfloat162float(__float2bfloat16(v3));
            const size_t o0 = (brow + row0) * C_DIM + col;
            const size_t o1 = (brow + row0 + 8) * C_DIM + col;
            *(uint32_t*)&ohi[o0] = pack_bf16(v0, v1);
            *(uint32_t*)&olo[o0] = pack_bf16(v0 - e0, v1 - e1);
            *(uint32_t*)&ohi[o1] = pack_bf16(v2, v3);
            *(uint32_t*)&olo[o1] = pack_bf16(v2 - e2, v3 - e3);
        }
    }
}

// ---------------------------------------------------------------------------
extern "C" void kernel_launch(void* const* d_in, const int* in_sizes, int n_in,
                              void* d_out, int out_size)
{
    const float* x      = (const float*)d_in[0];
    const float* qkv_w  = (const float*)d_in[1];
    const float* qkv_b  = (const float*)d_in[2];
    const float* out_w  = (const float*)d_in[3];
    const float* out_b  = (const float*)d_in[4];
    float* out = (float*)d_out;

    __nv_bfloat16 *qvh, *qvl, *xhi, *xlo, *ahi, *alo, *wqh, *wql, *woh, *wol;
    cudaGetSymbolAddress((void**)&qvh, g_qkvh);
    cudaGetSymbolAddress((void**)&qvl, g_qkvl);
    cudaGetSymbolAddress((void**)&xhi, g_xhi);
    cudaGetSymbolAddress((void**)&xlo, g_xlo);
    cudaGetSymbolAddress((void**)&ahi, g_ahi);
    cudaGetSymbolAddress((void**)&alo, g_alo);
    cudaGetSymbolAddress((void**)&wqh, g_wqt_hi);
    cudaGetSymbolAddress((void**)&wql, g_wqt_lo);
    cudaGetSymbolAddress((void**)&woh, g_wot_hi);
    cudaGetSymbolAddress((void**)&wol, g_wot_lo);

    cudaFuncSetAttribute(gemm_mma, cudaFuncAttributeMaxDynamicSharedMemorySize, SMEM_GEMM);
    cudaFuncSetAttribute(attn_mma, cudaFuncAttributeMaxDynamicSharedMemorySize, SMEM_ATT2);

    // Prepasses: split x; transpose+split weights
    split_k<<<(MTOT * C_DIM / 4 + 255) / 256, 256>>>(x, xhi, xlo, MTOT * C_DIM / 4);
    tsplit_k<<<dim3(C3 / 32, C_DIM / 32), dim3(32, 8)>>>(qkv_w, wqh, wql, C_DIM, C3);
    tsplit_k<<<dim3(C_DIM / 32, C_DIM / 32), dim3(32, 8)>>>(out_w, woh, wol, C_DIM, C_DIM);

    // 1) QKV projection -> split bf16 output (Q pre-scaled by 0.125)
    gemm_mma<<<dim3(C3 / 128, MTOT / 256), 256, SMEM_GEMM>>>(
        xhi, xlo, wqh, wql, qkv_b, nullptr, qvh, qvl, C3, 1);

    // 2) Causal MHA (256-query CTAs, all-bf16 data path, double-buffered)
    attn_mma<<<dim3(TT / 256, BB * HH), 256, SMEM_ATT2>>>(qvh, qvl, ahi, alo);

    // 3) Output projection -> fp32 final output
    gemm_mma<<<dim3(C_DIM / 128, MTOT / 256), 256, SMEM_GEMM>>>(
        ahi, alo, woh, wol, out_b, out, nullptr, nullptr, C_DIM, 0);
}

// round 9
// speedup vs baseline: 1.0868x; 1.0868x over previous
#include <cuda_runtime.h>
#include <cuda_bf16.h>
#include <cstdint>

#define C_DIM 1024
#define C3    3072
#define BB    2
#define TT    2048
#define HH    16
#define MTOT  4096   // BB*TT

// ---------------------------------------------------------------------------
// Scratch buffers (__device__ globals: the sanctioned no-alloc workaround)
// ---------------------------------------------------------------------------
__device__ __nv_bfloat16 g_qkvh[(size_t)MTOT * C3];     // QKV split hi (Q pre-scaled)
__device__ __nv_bfloat16 g_qkvl[(size_t)MTOT * C3];     // QKV split lo
__device__ __nv_bfloat16 g_xhi[(size_t)MTOT * C_DIM];
__device__ __nv_bfloat16 g_xlo[(size_t)MTOT * C_DIM];
__device__ __nv_bfloat16 g_ahi[(size_t)MTOT * C_DIM];   // attn out hi (K-major)
__device__ __nv_bfloat16 g_alo[(size_t)MTOT * C_DIM];   // attn out lo
__device__ __nv_bfloat16 g_wqt_hi[(size_t)C3 * C_DIM];  // qkv_w^T [N=3072][K=1024]
__device__ __nv_bfloat16 g_wqt_lo[(size_t)C3 * C_DIM];
__device__ __nv_bfloat16 g_wot_hi[(size_t)C_DIM * C_DIM];
__device__ __nv_bfloat16 g_wot_lo[(size_t)C_DIM * C_DIM];
__device__ unsigned g_tile_ctr;                         // persistent-GEMM work queue

// ---------------------------------------------------------------------------
// Portable tensor-core helpers (compute_103-safe: ldmatrix / mma.sync / cp.async)
// ---------------------------------------------------------------------------
__device__ __forceinline__ uint32_t smem_u32(const void* p) {
    uint32_t a;
    asm("{ .reg .u64 t; cvta.to.shared.u64 t, %1; cvt.u32.u64 %0, t; }"
        : "=r"(a) : "l"(p));
    return a;
}
#define SWZ128(off) ((off) ^ (((off) >> 3) & 0x70))

__device__ __forceinline__ void ldsm4(uint32_t* r, uint32_t addr) {
    asm volatile("ldmatrix.sync.aligned.m8n8.x4.shared.b16 {%0,%1,%2,%3}, [%4];"
        : "=r"(r[0]), "=r"(r[1]), "=r"(r[2]), "=r"(r[3]) : "r"(addr));
}
__device__ __forceinline__ void ldsm4t(uint32_t* r, uint32_t addr) {
    asm volatile("ldmatrix.sync.aligned.m8n8.x4.trans.shared.b16 {%0,%1,%2,%3}, [%4];"
        : "=r"(r[0]), "=r"(r[1]), "=r"(r[2]), "=r"(r[3]) : "r"(addr));
}
__device__ __forceinline__ void mma_bf16(float* d, const uint32_t* a, const uint32_t* b) {
    asm volatile("mma.sync.aligned.m16n8k16.row.col.f32.bf16.bf16.f32 "
        "{%0,%1,%2,%3}, {%4,%5,%6,%7}, {%8,%9}, {%0,%1,%2,%3};"
        : "+f"(d[0]), "+f"(d[1]), "+f"(d[2]), "+f"(d[3])
        : "r"(a[0]), "r"(a[1]), "r"(a[2]), "r"(a[3]), "r"(b[0]), "r"(b[1]));
}
#define CP16(dst, src)  asm volatile("cp.async.cg.shared.global [%0], [%1], 16;" :: "r"(dst), "l"(src) : "memory")
#define CP_COMMIT()     asm volatile("cp.async.commit_group;" ::: "memory")
#define CP_WAIT0()      asm volatile("cp.async.wait_group 0;" ::: "memory")
#define CP_WAIT1()      asm volatile("cp.async.wait_group 1;" ::: "memory")

__device__ __forceinline__ uint32_t pack_bf16(float a, float b) {
    __nv_bfloat162 p;
    p.x = __float2bfloat16(a);
    p.y = __float2bfloat16(b);
    return *(uint32_t*)&p;
}

// ---------------------------------------------------------------------------
// Prepass: fp32 -> (hi, lo) bf16 split.  n4 = element_count/4.
// ---------------------------------------------------------------------------
__global__ __launch_bounds__(256) void split_k(const float* __restrict__ in,
    __nv_bfloat16* __restrict__ hi, __nv_bfloat16* __restrict__ lo, int n4)
{
    const int i = blockIdx.x * 256 + threadIdx.x;
    if (i >= n4) return;
    const float4 v = ((const float4*)in)[i];
    __nv_bfloat16 h0 = __float2bfloat16(v.x), h1 = __float2bfloat16(v.y);
    __nv_bfloat16 h2 = __float2bfloat16(v.z), h3 = __float2bfloat16(v.w);
    __nv_bfloat162 hp0, hp1, lp0, lp1;
    hp0.x = h0; hp0.y = h1; hp1.x = h2; hp1.y = h3;
    lp0.x = __float2bfloat16(v.x - __bfloat162float(h0));
    lp0.y = __float2bfloat16(v.y - __bfloat162float(h1));
    lp1.x = __float2bfloat16(v.z - __bfloat162float(h2));
    lp1.y = __float2bfloat16(v.w - __bfloat162float(h3));
    ((__nv_bfloat162*)hi)[i * 2 + 0] = hp0;
    ((__nv_bfloat162*)hi)[i * 2 + 1] = hp1;
    ((__nv_bfloat162*)lo)[i * 2 + 0] = lp0;
    ((__nv_bfloat162*)lo)[i * 2 + 1] = lp1;
}

// ---------------------------------------------------------------------------
// Prepass: transpose + split.  in [K][N] fp32 -> out hi/lo [N][K] bf16.
// ---------------------------------------------------------------------------
__global__ __launch_bounds__(256) void tsplit_k(const float* __restrict__ in,
    __nv_bfloat16* __restrict__ hiT, __nv_bfloat16* __restrict__ loT, int K, int N)
{
    __shared__ float tile[32][33];
    const int n0 = blockIdx.x * 32, k0 = blockIdx.y * 32;
    const int tx = threadIdx.x, ty = threadIdx.y;
    for (int i = ty; i < 32; i += 8)
        tile[i][tx] = in[(size_t)(k0 + i) * N + n0 + tx];
    __syncthreads();
    for (int i = ty; i < 32; i += 8) {
        const float v = tile[tx][i];
        const __nv_bfloat16 h = __float2bfloat16(v);
        hiT[(size_t)(n0 + i) * K + k0 + tx] = h;
        loT[(size_t)(n0 + i) * K + k0 + tx] = __float2bfloat16(v - __bfloat162float(h));
    }
}

// ---------------------------------------------------------------------------
// Work-queue reset (1 thread; runs before each persistent GEMM launch)
// ---------------------------------------------------------------------------
__global__ void reset_ctr_k() { g_tile_ctr = 0u; }

// ---------------------------------------------------------------------------
// mma.sync GEMM v5 (persistent): C tiles of 256x128 pulled from an atomic
// work queue (148 CTAs, no wave-quantization tail). Warp tile 64x64
// (4M x 2N warps); B frags double-buffered per-ni; BK=64; 2-stage cp.async;
// smem 192KB; 1 CTA/SM.
// mode 0: fp32 out.  mode 1: hi/lo bf16 split out, Q block pre-scaled 0.125.
// ---------------------------------------------------------------------------
#define GA_B      32768                  // one A array (256 x 128B)
#define GB_B      16384                  // one B array (128 x 128B)
#define GSTAGE_B  (2 * GA_B + 2 * GB_B)  // 98304
#define SMEM_GEMM (2 * GSTAGE_B)         // 196608

__global__ __launch_bounds__(256, 1) void gemm_mma(
    const __nv_bfloat16* __restrict__ Ahi, const __nv_bfloat16* __restrict__ Alo,
    const __nv_bfloat16* __restrict__ Bhi, const __nv_bfloat16* __restrict__ Blo,
    const float* __restrict__ bias, float* __restrict__ Cf,
    __nv_bfloat16* __restrict__ Chi, __nv_bfloat16* __restrict__ Clo,
    int Ntot, int mode, int nx, int ntiles)
{
    extern __shared__ __align__(1024) char smg[];
    __shared__ unsigned s_tile;
    const uint32_t sb = smem_u32(smg);
    const int t = threadIdx.x, w = t >> 5, lane = t & 31;
    const int wm = (w >> 1) << 6, wn = (w & 1) << 6;
    const int aRow = wm + (lane & 15);
    const int bRow = wn + ((lane >> 4) << 3) + (lane & 7);

    for (;;) {
        if (t == 0) s_tile = atomicAdd(&g_tile_ctr, 1u);
        __syncthreads();
        const unsigned tile_id = s_tile;
        if (tile_id >= (unsigned)ntiles) break;
        const int m0 = (int)(tile_id / nx) << 8;
        const int n0 = (int)(tile_id % nx) << 7;

        const __nv_bfloat16* srcA[2] = { Ahi + (size_t)m0 * 1024, Alo + (size_t)m0 * 1024 };
        const __nv_bfloat16* srcB[2] = { Bhi + (size_t)n0 * 1024, Blo + (size_t)n0 * 1024 };

        float acc[4][8][4];
#pragma unroll
        for (int i = 0; i < 4; i++)
#pragma unroll
            for (int j = 0; j < 8; j++)
#pragma unroll
                for (int q = 0; q < 4; q++) acc[i][j][q] = 0.f;

        auto fill = [&](int c, int stg) {
            const int k0 = c << 6;
            const uint32_t stb = sb + stg * GSTAGE_B;
#pragma unroll
            for (int arr = 0; arr < 2; ++arr) {          // A hi/lo: 256 rows
                const uint32_t db = stb + arr * GA_B;
                const __nv_bfloat16* s = srcA[arr] + k0;
#pragma unroll
                for (int i = 0; i < 8; ++i) {
                    const int idx = t + (i << 8);        // 0..2047
                    const int row = idx >> 3, seg = idx & 7;
                    CP16(db + SWZ128(row * 128 + seg * 16),
                         s + (size_t)row * 1024 + seg * 8);
                }
            }
#pragma unroll
            for (int arr = 0; arr < 2; ++arr) {          // B hi/lo: 128 rows
                const uint32_t db = stb + 2 * GA_B + arr * GB_B;
                const __nv_bfloat16* s = srcB[arr] + k0;
#pragma unroll
                for (int i = 0; i < 4; ++i) {
                    const int idx = t + (i << 8);        // 0..1023
                    const int row = idx >> 3, seg = idx & 7;
                    CP16(db + SWZ128(row * 128 + seg * 16),
                         s + (size_t)row * 1024 + seg * 8);
                }
            }
        };

        fill(0, 0);
        CP_COMMIT();
        CP_WAIT0();
        __syncthreads();

        for (int c = 0; c < 16; ++c) {
            const int stg = c & 1;
            if (c < 15) { fill(c + 1, stg ^ 1); CP_COMMIT(); }

            const uint32_t stA_h = sb + stg * GSTAGE_B;
            const uint32_t stA_l = stA_h + GA_B;
            const uint32_t stB_h = stA_h + 2 * GA_B;
            const uint32_t stB_l = stB_h + GB_B;

#pragma unroll
            for (int k16 = 0; k16 < 4; ++k16) {
                const int kbA = k16 * 32 + ((lane >> 4) & 1) * 16;
                const int kbB = k16 * 32 + ((lane >> 3) & 1) * 16;

                uint32_t aH[4][4], aL[4][4];
#pragma unroll
                for (int mi = 0; mi < 4; ++mi) {
                    const uint32_t off = SWZ128((aRow + mi * 16) * 128 + kbA);
                    ldsm4(aH[mi], stA_h + off);
                    ldsm4(aL[mi], stA_l + off);
                }
                uint32_t bH[2][4], bL[2][4];
                {
                    const uint32_t off = SWZ128(bRow * 128 + kbB);
                    ldsm4(bH[0], stB_h + off);
                    ldsm4(bL[0], stB_l + off);
                }
#pragma unroll
                for (int ni = 0; ni < 4; ++ni) {
                    const int cur = ni & 1;
                    if (ni < 3) {
                        const uint32_t off = SWZ128((bRow + (ni + 1) * 16) * 128 + kbB);
                        ldsm4(bH[cur ^ 1], stB_h + off);
                        ldsm4(bL[cur ^ 1], stB_l + off);
                    }
#pragma unroll
                    for (int mi = 0; mi < 4; ++mi)
#pragma unroll
                        for (int h2 = 0; h2 < 2; ++h2) {
                            float* d = acc[mi][ni * 2 + h2];
                            mma_bf16(d, aH[mi], &bH[cur][h2 * 2]);
                            mma_bf16(d, aH[mi], &bL[cur][h2 * 2]);
                            mma_bf16(d, aL[mi], &bH[cur][h2 * 2]);
                        }
                }
            }
            CP_WAIT0();
            __syncthreads();
        }

        const int g2 = lane >> 2, tg = lane & 3;
        if (mode == 0) {
#pragma unroll
            for (int mi = 0; mi < 4; ++mi) {
                const int row0 = m0 + wm + mi * 16 + g2;
#pragma unroll
                for (int j = 0; j < 8; ++j) {
                    const int col = n0 + wn + j * 8 + tg * 2;
                    const float2 b2 = *(const float2*)&bias[col];
                    const float* d = acc[mi][j];
                    float2 lo2 = { d[0] + b2.x, d[1] + b2.y };
                    float2 hi2 = { d[2] + b2.x, d[3] + b2.y };
                    *(float2*)&Cf[(size_t)row0 * Ntot + col] = lo2;
                    *(float2*)&Cf[(size_t)(row0 + 8) * Ntot + col] = hi2;
                }
            }
        } else {
            const float scale = (n0 < C_DIM) ? 0.125f : 1.0f;   // Q block pre-scale
#pragma unroll
            for (int mi = 0; mi < 4; ++mi) {
                const int row0 = m0 + wm + mi * 16 + g2;
#pragma unroll
                for (int j = 0; j < 8; ++j) {
                    const int col = n0 + wn + j * 8 + tg * 2;
                    const float2 b2 = *(const float2*)&bias[col];
                    const float* d = acc[mi][j];
                    const float v0 = (d[0] + b2.x) * scale, v1 = (d[1] + b2.y) * scale;
                    const float v2 = (d[2] + b2.x) * scale, v3 = (d[3] + b2.y) * scale;
                    const float e0 = __bfloat162float(__float2bfloat16(v0));
                    const float e1 = __bfloat162float(__float2bfloat16(v1));
                    const float e2 = __bfloat162float(__float2bfloat16(v2));
                    const float e3 = __bfloat162float(__float2bfloat16(v3));
                    const size_t o0 = (size_t)row0 * Ntot + col;
                    const size_t o1 = (size_t)(row0 + 8) * Ntot + col;
                    *(uint32_t*)&Chi[o0] = pack_bf16(v0, v1);
                    *(uint32_t*)&Clo[o0] = pack_bf16(v0 - e0, v1 - e1);
                    *(uint32_t*)&Chi[o1] = pack_bf16(v2, v3);
                    *(uint32_t*)&Clo[o1] = pack_bf16(v2 - e2, v3 - e3);
                }
            }
        }
        __syncthreads();   // all lanes done with smem/s_tile before next steal
    }
}

// ---------------------------------------------------------------------------
// Flash attention (reverted to the R7-passing 128-query version): all-bf16
// split inputs via cp.async, double-buffered K/V, Q frags hoisted,
// V row-major + ldmatrix.trans. 8 warps x 16 rows; key tiles of 64.
// Smem: Qh,Ql[128][64] (32KB) + 2 stages x {Kh,Kl,Vh,Vl}[64][64] (64KB) = 96KB.
// ---------------------------------------------------------------------------
#define SMEM_ATT2 98304

__global__ __launch_bounds__(256) void attn_mma(
    const __nv_bfloat16* __restrict__ qh, const __nv_bfloat16* __restrict__ ql,
    __nv_bfloat16* __restrict__ ohi, __nv_bfloat16* __restrict__ olo)
{
    extern __shared__ __align__(1024) char sma[];
    const uint32_t sb  = smem_u32(sma);
    const uint32_t sQh = sb, sQl = sb + 16384;

    const int t = threadIdx.x, w = t >> 5, lane = t & 31;
    const int g = lane >> 2, tq = lane & 3;
    const int qi = gridDim.x - 1 - blockIdx.x;      // heavy tiles first
    const int bh = blockIdx.y, b = bh >> 4, h = bh & 15;
    const int qbase = qi << 7;
    const size_t brow = (size_t)b * TT;
    const int wm = w << 4;
    const int hcol = h * 64;

    auto fillQ = [&]() {
#pragma unroll
        for (int i = 0; i < 8; ++i) {
            const int idx = t + (i << 8);            // 0..2047
            const int arr = idx >> 10;               // 0 hi, 1 lo
            const int r = (idx >> 3) & 127, seg = idx & 7;
            const __nv_bfloat16* src =
                (arr ? ql : qh) + (brow + qbase + r) * C3 + hcol + seg * 8;
            CP16((arr ? sQl : sQh) + SWZ128(r * 128 + seg * 16), src);
        }
    };
    auto fillKV = [&](int kt, int buf) {
        const int kb = kt << 6;
        const uint32_t sbase = sb + 32768 + buf * 32768;
#pragma unroll
        for (int i = 0; i < 8; ++i) {
            const int idx = t + (i << 8);            // 0..2047
            const int arr = idx >> 9;                // 0 Kh, 1 Kl, 2 Vh, 3 Vl
            const int r = (idx >> 3) & 63, seg = idx & 7;
            const int colbase = ((arr < 2) ? C_DIM : 2 * C_DIM) + hcol;
            const __nv_bfloat16* src =
                ((arr & 1) ? ql : qh) + (brow + kb + r) * C3 + colbase + seg * 8;
            CP16(sbase + arr * 8192 + SWZ128(r * 128 + seg * 16), src);
        }
    };

    float oacc[8][4];
#pragma unroll
    for (int j = 0; j < 8; ++j)
#pragma unroll
        for (int q = 0; q < 4; ++q) oacc[j][q] = 0.f;
    float mrow[2] = { -1e30f, -1e30f };
    float lrow[2] = { 0.f, 0.f };

    const int aRow  = wm + (lane & 15);
    const int bRowS = ((lane >> 4) << 3) + (lane & 7);
    const int ntiles = 2 * qi + 2;

    uint32_t aQh[4][4], aQl[4][4];                   // Q frags, hoisted

    fillQ();
    fillKV(0, 0);
    CP_COMMIT();

    for (int kt = 0; kt < ntiles; ++kt) {
        const int kb = kt << 6;
        const uint32_t sKh = sb + 32768 + (kt & 1) * 32768;
        const uint32_t sKl = sKh + 8192, sVh = sKh + 16384, sVl = sKh + 24576;

        if (kt + 1 < ntiles) {
            fillKV(kt + 1, (kt + 1) & 1);
            CP_COMMIT();
            CP_WAIT1();
        } else {
            CP_WAIT0();
        }
        __syncthreads();

        if (kt == 0) {
#pragma unroll
            for (int k16 = 0; k16 < 4; ++k16) {
                const int kbA = k16 * 32 + ((lane >> 4) & 1) * 16;
                const uint32_t offA = SWZ128(aRow * 128 + kbA);
                ldsm4(aQh[k16], sQh + offA);
                ldsm4(aQl[k16], sQl + offA);
            }
        }

        // ---- S = Q K^T (split, fp32 accum) ----
        float sacc[8][4];
#pragma unroll
        for (int j = 0; j < 8; ++j)
#pragma unroll
            for (int q = 0; q < 4; ++q) sacc[j][q] = 0.f;

#pragma unroll
        for (int k16 = 0; k16 < 4; ++k16) {
            const int kbB = k16 * 32 + ((lane >> 3) & 1) * 16;
            uint32_t bH[4][4], bL[4][4];
#pragma unroll
            for (int ni = 0; ni < 4; ++ni) {
                const uint32_t off = SWZ128((bRowS + ni * 16) * 128 + kbB);
                ldsm4(bH[ni], sKh + off);
                ldsm4(bL[ni], sKl + off);
            }
#pragma unroll
            for (int ni = 0; ni < 4; ++ni)
#pragma unroll
                for (int h2 = 0; h2 < 2; ++h2) {
                    float* d = sacc[ni * 2 + h2];
                    mma_bf16(d, aQh[k16], &bH[ni][h2 * 2]);
                    mma_bf16(d, aQh[k16], &bL[ni][h2 * 2]);
                    mma_bf16(d, aQl[k16], &bH[ni][h2 * 2]);
                }
        }

        // ---- causal mask (only last two tiles cross the diagonal) ----
        if (kt >= 2 * qi) {
            const int row0 = qbase + wm + g;
#pragma unroll
            for (int j = 0; j < 8; ++j) {
                const int col = kb + j * 8 + tq * 2;
                if (col     > row0)     sacc[j][0] = -1e30f;
                if (col + 1 > row0)     sacc[j][1] = -1e30f;
                if (col     > row0 + 8) sacc[j][2] = -1e30f;
                if (col + 1 > row0 + 8) sacc[j][3] = -1e30f;
            }
        }

        // ---- online softmax (2 rows/thread, quad reductions) ----
#pragma unroll
        for (int rr = 0; rr < 2; ++rr) {
            const int i0 = rr * 2;
            float mt = -1e30f;
#pragma unroll
            for (int j = 0; j < 8; ++j)
                mt = fmaxf(mt, fmaxf(sacc[j][i0], sacc[j][i0 + 1]));
            mt = fmaxf(mt, __shfl_xor_sync(0xffffffffu, mt, 1));
            mt = fmaxf(mt, __shfl_xor_sync(0xffffffffu, mt, 2));
            const float mn = fmaxf(mrow[rr], mt);
            const float alpha = __expf(mrow[rr] - mn);
            mrow[rr] = mn;
            float ps = 0.f;
#pragma unroll
            for (int j = 0; j < 8; ++j) {
                const float p0 = __expf(sacc[j][i0] - mn);
                const float p1 = __expf(sacc[j][i0 + 1] - mn);
                sacc[j][i0] = p0; sacc[j][i0 + 1] = p1;
                ps += p0 + p1;
            }
            ps += __shfl_xor_sync(0xffffffffu, ps, 1);
            ps += __shfl_xor_sync(0xffffffffu, ps, 2);
            lrow[rr] = lrow[rr] * alpha + ps;
#pragma unroll
            for (int j = 0; j < 8; ++j) {
                oacc[j][i0] *= alpha;
                oacc[j][i0 + 1] *= alpha;
            }
        }

        // ---- O += P V (P split register-direct; V via ldmatrix.trans) ----
#pragma unroll
        for (int kk = 0; kk < 4; ++kk) {
            const float* s0 = sacc[2 * kk];
            const float* s1 = sacc[2 * kk + 1];
            uint32_t aPh[4], aPl[4];
            {
                float h00 = __bfloat162float(__float2bfloat16(s0[0]));
                float h01 = __bfloat162float(__float2bfloat16(s0[1]));
                float h02 = __bfloat162float(__float2bfloat16(s0[2]));
                float h03 = __bfloat162float(__float2bfloat16(s0[3]));
                float h10 = __bfloat162float(__float2bfloat16(s1[0]));
                float h11 = __bfloat162float(__float2bfloat16(s1[1]));
                float h12 = __bfloat162float(__float2bfloat16(s1[2]));
                float h13 = __bfloat162float(__float2bfloat16(s1[3]));
                aPh[0] = pack_bf16(s0[0], s0[1]);
                aPh[1] = pack_bf16(s0[2], s0[3]);
                aPh[2] = pack_bf16(s1[0], s1[1]);
                aPh[3] = pack_bf16(s1[2], s1[3]);
                aPl[0] = pack_bf16(s0[0] - h00, s0[1] - h01);
                aPl[1] = pack_bf16(s0[2] - h02, s0[3] - h03);
                aPl[2] = pack_bf16(s1[0] - h10, s1[1] - h11);
                aPl[3] = pack_bf16(s1[2] - h12, s1[3] - h13);
            }
            const int vr = kk * 16 + (lane & 15);
            const int vc = ((lane >> 4) & 1) * 16;
            uint32_t vH[4][4], vL[4][4];
#pragma unroll
            for (int ni = 0; ni < 4; ++ni) {
                const uint32_t off = SWZ128(vr * 128 + ni * 32 + vc);
                ldsm4t(vH[ni], sVh + off);
                ldsm4t(vL[ni], sVl + off);
            }
#pragma unroll
            for (int ni = 0; ni < 4; ++ni)
#pragma unroll
                for (int h2 = 0; h2 < 2; ++h2) {
                    float* d = oacc[ni * 2 + h2];
                    mma_bf16(d, aPh, &vH[ni][h2 * 2]);
                    mma_bf16(d, aPh, &vL[ni][h2 * 2]);
                    mma_bf16(d, aPl, &vH[ni][h2 * 2]);
                }
        }
        __syncthreads();
    }

    // ---- epilogue: normalize, split hi/lo, store (K-major [M][1024]) ----
    const float inv0 = 1.f / lrow[0];
    const float inv1 = 1.f / lrow[1];
    const int row0 = qbase + wm + g;
#pragma unroll
    for (int j = 0; j < 8; ++j) {
        const int col = hcol + j * 8 + tq * 2;
        const float v0 = oacc[j][0] * inv0, v1 = oacc[j][1] * inv0;
        const float v2 = oacc[j][2] * inv1, v3 = oacc[j][3] * inv1;
        const float e0 = __bfloat162float(__float2bfloat16(v0));
        const float e1 = __bfloat162float(__float2bfloat16(v1));
        const float e2 = __bfloat162float(__float2bfloat16(v2));
        const float e3 = __bfloat162float(__float2bfloat16(v3));
        const size_t o0 = (brow + row0) * C_DIM + col;
        const size_t o1 = (brow + row0 + 8) * C_DIM + col;
        *(uint32_t*)&ohi[o0] = pack_bf16(v0, v1);
        *(uint32_t*)&olo[o0] = pack_bf16(v0 - e0, v1 - e1);
        *(uint32_t*)&ohi[o1] = pack_bf16(v2, v3);
        *(uint32_t*)&olo[o1] = pack_bf16(v2 - e2, v3 - e3);
    }
}

// ---------------------------------------------------------------------------
extern "C" void kernel_launch(void* const* d_in, const int* in_sizes, int n_in,
                              void* d_out, int out_size)
{
    const float* x      = (const float*)d_in[0];
    const float* qkv_w  = (const float*)d_in[1];
    const float* qkv_b  = (const float*)d_in[2];
    const float* out_w  = (const float*)d_in[3];
    const float* out_b  = (const float*)d_in[4];
    float* out = (float*)d_out;

    __nv_bfloat16 *qvh, *qvl, *xhi, *xlo, *ahi, *alo, *wqh, *wql, *woh, *wol;
    cudaGetSymbolAddress((void**)&qvh, g_qkvh);
    cudaGetSymbolAddress((void**)&qvl, g_qkvl);
    cudaGetSymbolAddress((void**)&xhi, g_xhi);
    cudaGetSymbolAddress((void**)&xlo, g_xlo);
    cudaGetSymbolAddress((void**)&ahi, g_ahi);
    cudaGetSymbolAddress((void**)&alo, g_alo);
    cudaGetSymbolAddress((void**)&wqh, g_wqt_hi);
    cudaGetSymbolAddress((void**)&wql, g_wqt_lo);
    cudaGetSymbolAddress((void**)&woh, g_wot_hi);
    cudaGetSymbolAddress((void**)&wol, g_wot_lo);

    cudaFuncSetAttribute(gemm_mma, cudaFuncAttributeMaxDynamicSharedMemorySize, SMEM_GEMM);
    cudaFuncSetAttribute(attn_mma, cudaFuncAttributeMaxDynamicSharedMemorySize, SMEM_ATT2);

    // Prepasses: split x; transpose+split weights
    split_k<<<(MTOT * C_DIM / 4 + 255) / 256, 256>>>(x, xhi, xlo, MTOT * C_DIM / 4);
    tsplit_k<<<dim3(C3 / 32, C_DIM / 32), dim3(32, 8)>>>(qkv_w, wqh, wql, C_DIM, C3);
    tsplit_k<<<dim3(C_DIM / 32, C_DIM / 32), dim3(32, 8)>>>(out_w, woh, wol, C_DIM, C_DIM);

    // 1) QKV projection -> split bf16 output (persistent work-stealing)
    reset_ctr_k<<<1, 1>>>();
    gemm_mma<<<148, 256, SMEM_GEMM>>>(
        xhi, xlo, wqh, wql, qkv_b, nullptr, qvh, qvl, C3, 1,
        C3 / 128, (C3 / 128) * (MTOT / 256));

    // 2) Causal MHA (128-query CTAs, all-bf16 data path, double-buffered)
    attn_mma<<<dim3(TT / 128, BB * HH), 256, SMEM_ATT2>>>(qvh, qvl, ahi, alo);

    // 3) Output projection -> fp32 final output (persistent work-stealing)
    reset_ctr_k<<<1, 1>>>();
    gemm_mma<<<148, 256, SMEM_GEMM>>>(
        ahi, alo, woh, wol, out_b, out, nullptr, nullptr, C_DIM, 0,
        C_DIM / 128, (C_DIM / 128) * (MTOT / 256));
}

// round 10
// speedup vs baseline: 1.1530x; 1.0610x over previous
#include <cuda_runtime.h>
#include <cuda_bf16.h>
#include <cstdint>

#define C_DIM 1024
#define C3    3072
#define BB    2
#define TT    2048
#define HH    16
#define MTOT  4096   // BB*TT

// ---------------------------------------------------------------------------
// Scratch buffers (__device__ globals: the sanctioned no-alloc workaround)
// ---------------------------------------------------------------------------
__device__ __nv_bfloat16 g_qkvh[(size_t)MTOT * C3];     // QKV split hi (Q pre-scaled)
__device__ __nv_bfloat16 g_qkvl[(size_t)MTOT * C3];     // QKV split lo
__device__ __nv_bfloat16 g_xhi[(size_t)MTOT * C_DIM];
__device__ __nv_bfloat16 g_xlo[(size_t)MTOT * C_DIM];
__device__ __nv_bfloat16 g_ahi[(size_t)MTOT * C_DIM];   // attn out hi (K-major)
__device__ __nv_bfloat16 g_alo[(size_t)MTOT * C_DIM];   // attn out lo
__device__ __nv_bfloat16 g_wqt_hi[(size_t)C3 * C_DIM];  // qkv_w^T [N=3072][K=1024]
__device__ __nv_bfloat16 g_wqt_lo[(size_t)C3 * C_DIM];
__device__ __nv_bfloat16 g_wot_hi[(size_t)C_DIM * C_DIM];
__device__ __nv_bfloat16 g_wot_lo[(size_t)C_DIM * C_DIM];

// ---------------------------------------------------------------------------
// Portable tensor-core helpers (compute_103-safe: ldmatrix / mma.sync / cp.async)
// ---------------------------------------------------------------------------
__device__ __forceinline__ uint32_t smem_u32(const void* p) {
    uint32_t a;
    asm("{ .reg .u64 t; cvta.to.shared.u64 t, %1; cvt.u32.u64 %0, t; }"
        : "=r"(a) : "l"(p));
    return a;
}
#define SWZ128(off) ((off) ^ (((off) >> 3) & 0x70))

__device__ __forceinline__ void ldsm4(uint32_t* r, uint32_t addr) {
    asm volatile("ldmatrix.sync.aligned.m8n8.x4.shared.b16 {%0,%1,%2,%3}, [%4];"
        : "=r"(r[0]), "=r"(r[1]), "=r"(r[2]), "=r"(r[3]) : "r"(addr));
}
__device__ __forceinline__ void ldsm4t(uint32_t* r, uint32_t addr) {
    asm volatile("ldmatrix.sync.aligned.m8n8.x4.trans.shared.b16 {%0,%1,%2,%3}, [%4];"
        : "=r"(r[0]), "=r"(r[1]), "=r"(r[2]), "=r"(r[3]) : "r"(addr));
}
__device__ __forceinline__ void mma_bf16(float* d, const uint32_t* a, const uint32_t* b) {
    asm volatile("mma.sync.aligned.m16n8k16.row.col.f32.bf16.bf16.f32 "
        "{%0,%1,%2,%3}, {%4,%5,%6,%7}, {%8,%9}, {%0,%1,%2,%3};"
        : "+f"(d[0]), "+f"(d[1]), "+f"(d[2]), "+f"(d[3])
        : "r"(a[0]), "r"(a[1]), "r"(a[2]), "r"(a[3]), "r"(b[0]), "r"(b[1]));
}
#define CP16(dst, src)  asm volatile("cp.async.cg.shared.global [%0], [%1], 16;" :: "r"(dst), "l"(src) : "memory")
#define CP_COMMIT()     asm volatile("cp.async.commit_group;" ::: "memory")
#define CP_WAIT0()      asm volatile("cp.async.wait_group 0;" ::: "memory")
#define CP_WAIT1()      asm volatile("cp.async.wait_group 1;" ::: "memory")

__device__ __forceinline__ uint32_t pack_bf16(float a, float b) {
    __nv_bfloat162 p;
    p.x = __float2bfloat16(a);
    p.y = __float2bfloat16(b);
    return *(uint32_t*)&p;
}

// ---------------------------------------------------------------------------
// Prepass: fp32 -> (hi, lo) bf16 split.  n4 = element_count/4.
// ---------------------------------------------------------------------------
__global__ __launch_bounds__(256) void split_k(const float* __restrict__ in,
    __nv_bfloat16* __restrict__ hi, __nv_bfloat16* __restrict__ lo, int n4)
{
    const int i = blockIdx.x * 256 + threadIdx.x;
    if (i >= n4) return;
    const float4 v = ((const float4*)in)[i];
    __nv_bfloat16 h0 = __float2bfloat16(v.x), h1 = __float2bfloat16(v.y);
    __nv_bfloat16 h2 = __float2bfloat16(v.z), h3 = __float2bfloat16(v.w);
    __nv_bfloat162 hp0, hp1, lp0, lp1;
    hp0.x = h0; hp0.y = h1; hp1.x = h2; hp1.y = h3;
    lp0.x = __float2bfloat16(v.x - __bfloat162float(h0));
    lp0.y = __float2bfloat16(v.y - __bfloat162float(h1));
    lp1.x = __float2bfloat16(v.z - __bfloat162float(h2));
    lp1.y = __float2bfloat16(v.w - __bfloat162float(h3));
    ((__nv_bfloat162*)hi)[i * 2 + 0] = hp0;
    ((__nv_bfloat162*)hi)[i * 2 + 1] = hp1;
    ((__nv_bfloat162*)lo)[i * 2 + 0] = lp0;
    ((__nv_bfloat162*)lo)[i * 2 + 1] = lp1;
}

// ---------------------------------------------------------------------------
// Prepass: transpose + split.  in [K][N] fp32 -> out hi/lo [N][K] bf16.
// ---------------------------------------------------------------------------
__global__ __launch_bounds__(256) void tsplit_k(const float* __restrict__ in,
    __nv_bfloat16* __restrict__ hiT, __nv_bfloat16* __restrict__ loT, int K, int N)
{
    __shared__ float tile[32][33];
    const int n0 = blockIdx.x * 32, k0 = blockIdx.y * 32;
    const int tx = threadIdx.x, ty = threadIdx.y;
    for (int i = ty; i < 32; i += 8)
        tile[i][tx] = in[(size_t)(k0 + i) * N + n0 + tx];
    __syncthreads();
    for (int i = ty; i < 32; i += 8) {
        const float v = tile[tx][i];
        const __nv_bfloat16 h = __float2bfloat16(v);
        hiT[(size_t)(n0 + i) * K + k0 + tx] = h;
        loT[(size_t)(n0 + i) * K + k0 + tx] = __float2bfloat16(v - __bfloat162float(h));
    }
}

// ---------------------------------------------------------------------------
// mma.sync GEMM v6 (static persistent): 256x128 C tiles, tile_id strided by
// gridDim (uniform cost -> static schedule, no atomics). Warp tile 64x64;
// B frags double-buffered per-ni; BK=64; 2-stage cp.async; smem 192KB.
// mode 0: fp32 out.  mode 1: hi/lo bf16 split out, Q block pre-scaled 0.125.
// ---------------------------------------------------------------------------
#define GA_B      32768                  // one A array (256 x 128B)
#define GB_B      16384                  // one B array (128 x 128B)
#define GSTAGE_B  (2 * GA_B + 2 * GB_B)  // 98304
#define SMEM_GEMM (2 * GSTAGE_B)         // 196608

__global__ __launch_bounds__(256, 1) void gemm_mma(
    const __nv_bfloat16* __restrict__ Ahi, const __nv_bfloat16* __restrict__ Alo,
    const __nv_bfloat16* __restrict__ Bhi, const __nv_bfloat16* __restrict__ Blo,
    const float* __restrict__ bias, float* __restrict__ Cf,
    __nv_bfloat16* __restrict__ Chi, __nv_bfloat16* __restrict__ Clo,
    int Ntot, int mode, int nx, int ntiles)
{
    extern __shared__ __align__(1024) char smg[];
    const uint32_t sb = smem_u32(smg);
    const int t = threadIdx.x, w = t >> 5, lane = t & 31;
    const int wm = (w >> 1) << 6, wn = (w & 1) << 6;
    const int aRow = wm + (lane & 15);
    const int bRow = wn + ((lane >> 4) << 3) + (lane & 7);

    for (int tile_id = blockIdx.x; tile_id < ntiles; tile_id += gridDim.x) {
        const int m0 = (tile_id / nx) << 8;
        const int n0 = (tile_id % nx) << 7;

        const __nv_bfloat16* srcA[2] = { Ahi + (size_t)m0 * 1024, Alo + (size_t)m0 * 1024 };
        const __nv_bfloat16* srcB[2] = { Bhi + (size_t)n0 * 1024, Blo + (size_t)n0 * 1024 };

        float acc[4][8][4];
#pragma unroll
        for (int i = 0; i < 4; i++)
#pragma unroll
            for (int j = 0; j < 8; j++)
#pragma unroll
                for (int q = 0; q < 4; q++) acc[i][j][q] = 0.f;

        auto fill = [&](int c, int stg) {
            const int k0 = c << 6;
            const uint32_t stb = sb + stg * GSTAGE_B;
#pragma unroll
            for (int arr = 0; arr < 2; ++arr) {          // A hi/lo: 256 rows
                const uint32_t db = stb + arr * GA_B;
                const __nv_bfloat16* s = srcA[arr] + k0;
#pragma unroll
                for (int i = 0; i < 8; ++i) {
                    const int idx = t + (i << 8);        // 0..2047
                    const int row = idx >> 3, seg = idx & 7;
                    CP16(db + SWZ128(row * 128 + seg * 16),
                         s + (size_t)row * 1024 + seg * 8);
                }
            }
#pragma unroll
            for (int arr = 0; arr < 2; ++arr) {          // B hi/lo: 128 rows
                const uint32_t db = stb + 2 * GA_B + arr * GB_B;
                const __nv_bfloat16* s = srcB[arr] + k0;
#pragma unroll
                for (int i = 0; i < 4; ++i) {
                    const int idx = t + (i << 8);        // 0..1023
                    const int row = idx >> 3, seg = idx & 7;
                    CP16(db + SWZ128(row * 128 + seg * 16),
                         s + (size_t)row * 1024 + seg * 8);
                }
            }
        };

        fill(0, 0);
        CP_COMMIT();
        CP_WAIT0();
        __syncthreads();

        for (int c = 0; c < 16; ++c) {
            const int stg = c & 1;
            if (c < 15) { fill(c + 1, stg ^ 1); CP_COMMIT(); }

            const uint32_t stA_h = sb + stg * GSTAGE_B;
            const uint32_t stA_l = stA_h + GA_B;
            const uint32_t stB_h = stA_h + 2 * GA_B;
            const uint32_t stB_l = stB_h + GB_B;

#pragma unroll
            for (int k16 = 0; k16 < 4; ++k16) {
                const int kbA = k16 * 32 + ((lane >> 4) & 1) * 16;
                const int kbB = k16 * 32 + ((lane >> 3) & 1) * 16;

                uint32_t aH[4][4], aL[4][4];
#pragma unroll
                for (int mi = 0; mi < 4; ++mi) {
                    const uint32_t off = SWZ128((aRow + mi * 16) * 128 + kbA);
                    ldsm4(aH[mi], stA_h + off);
                    ldsm4(aL[mi], stA_l + off);
                }
                uint32_t bH[2][4], bL[2][4];
                {
                    const uint32_t off = SWZ128(bRow * 128 + kbB);
                    ldsm4(bH[0], stB_h + off);
                    ldsm4(bL[0], stB_l + off);
                }
#pragma unroll
                for (int ni = 0; ni < 4; ++ni) {
                    const int cur = ni & 1;
                    if (ni < 3) {
                        const uint32_t off = SWZ128((bRow + (ni + 1) * 16) * 128 + kbB);
                        ldsm4(bH[cur ^ 1], stB_h + off);
                        ldsm4(bL[cur ^ 1], stB_l + off);
                    }
#pragma unroll
                    for (int mi = 0; mi < 4; ++mi)
#pragma unroll
                        for (int h2 = 0; h2 < 2; ++h2) {
                            float* d = acc[mi][ni * 2 + h2];
                            mma_bf16(d, aH[mi], &bH[cur][h2 * 2]);
                            mma_bf16(d, aH[mi], &bL[cur][h2 * 2]);
                            mma_bf16(d, aL[mi], &bH[cur][h2 * 2]);
                        }
                }
            }
            CP_WAIT0();
            __syncthreads();
        }

        const int g2 = lane >> 2, tg = lane & 3;
        if (mode == 0) {
#pragma unroll
            for (int mi = 0; mi < 4; ++mi) {
                const int row0 = m0 + wm + mi * 16 + g2;
#pragma unroll
                for (int j = 0; j < 8; ++j) {
                    const int col = n0 + wn + j * 8 + tg * 2;
                    const float2 b2 = *(const float2*)&bias[col];
                    const float* d = acc[mi][j];
                    float2 lo2 = { d[0] + b2.x, d[1] + b2.y };
                    float2 hi2 = { d[2] + b2.x, d[3] + b2.y };
                    *(float2*)&Cf[(size_t)row0 * Ntot + col] = lo2;
                    *(float2*)&Cf[(size_t)(row0 + 8) * Ntot + col] = hi2;
                }
            }
        } else {
            const float scale = (n0 < C_DIM) ? 0.125f : 1.0f;   // Q block pre-scale
#pragma unroll
            for (int mi = 0; mi < 4; ++mi) {
                const int row0 = m0 + wm + mi * 16 + g2;
#pragma unroll
                for (int j = 0; j < 8; ++j) {
                    const int col = n0 + wn + j * 8 + tg * 2;
                    const float2 b2 = *(const float2*)&bias[col];
                    const float* d = acc[mi][j];
                    const float v0 = (d[0] + b2.x) * scale, v1 = (d[1] + b2.y) * scale;
                    const float v2 = (d[2] + b2.x) * scale, v3 = (d[3] + b2.y) * scale;
                    const float e0 = __bfloat162float(__float2bfloat16(v0));
                    const float e1 = __bfloat162float(__float2bfloat16(v1));
                    const float e2 = __bfloat162float(__float2bfloat16(v2));
                    const float e3 = __bfloat162float(__float2bfloat16(v3));
                    const size_t o0 = (size_t)row0 * Ntot + col;
                    const size_t o1 = (size_t)(row0 + 8) * Ntot + col;
                    *(uint32_t*)&Chi[o0] = pack_bf16(v0, v1);
                    *(uint32_t*)&Clo[o0] = pack_bf16(v0 - e0, v1 - e1);
                    *(uint32_t*)&Chi[o1] = pack_bf16(v2, v3);
                    *(uint32_t*)&Clo[o1] = pack_bf16(v2 - e2, v3 - e3);
                }
            }
        }
        __syncthreads();   // smem safe for next tile's fill
    }
}

// ---------------------------------------------------------------------------
// Flash attention v4: key tiles of 128 (halves per-key softmax overhead).
// CTA = 128 queries x one (b,h); 8 warps x 16 rows; ntiles = qi+1.
// Smem: Qh,Ql[128][64] (32KB) + 2 stages x {Kh,Kl,Vh,Vl}[128][64] (128KB) = 160KB.
// B frags rolled (double-buffered) per ni like the GEMM; V via ldmatrix.trans.
// ---------------------------------------------------------------------------
#define SMEM_ATT2 163840

__global__ __launch_bounds__(256) void attn_mma(
    const __nv_bfloat16* __restrict__ qh, const __nv_bfloat16* __restrict__ ql,
    __nv_bfloat16* __restrict__ ohi, __nv_bfloat16* __restrict__ olo)
{
    extern __shared__ __align__(1024) char sma[];
    const uint32_t sb  = smem_u32(sma);
    const uint32_t sQh = sb, sQl = sb + 16384;

    const int t = threadIdx.x, w = t >> 5, lane = t & 31;
    const int g = lane >> 2, tq = lane & 3;
    const int qi = gridDim.x - 1 - blockIdx.x;      // heavy tiles first
    const int bh = blockIdx.y, b = bh >> 4, h = bh & 15;
    const int qbase = qi << 7;
    const size_t brow = (size_t)b * TT;
    const int wm = w << 4;
    const int hcol = h * 64;

    auto fillQ = [&]() {
#pragma unroll
        for (int i = 0; i < 8; ++i) {
            const int idx = t + (i << 8);            // 0..2047
            const int arr = idx >> 10;               // 0 hi, 1 lo
            const int r = (idx >> 3) & 127, seg = idx & 7;
            const __nv_bfloat16* src =
                (arr ? ql : qh) + (brow + qbase + r) * C3 + hcol + seg * 8;
            CP16((arr ? sQl : sQh) + SWZ128(r * 128 + seg * 16), src);
        }
    };
    // K/V tile of 128 keys: 4 arrays x 128 rows x 128B = 64KB per stage
    auto fillKV = [&](int kt, int buf) {
        const int kb = kt << 7;
        const uint32_t sbase = sb + 32768 + buf * 65536;
#pragma unroll
        for (int i = 0; i < 16; ++i) {
            const int idx = t + (i << 8);            // 0..4095
            const int arr = idx >> 10;               // 0 Kh, 1 Kl, 2 Vh, 3 Vl
            const int r = (idx >> 3) & 127, seg = idx & 7;
            const int colbase = ((arr < 2) ? C_DIM : 2 * C_DIM) + hcol;
            const __nv_bfloat16* src =
                ((arr & 1) ? ql : qh) + (brow + kb + r) * C3 + colbase + seg * 8;
            CP16(sbase + arr * 16384 + SWZ128(r * 128 + seg * 16), src);
        }
    };

    float oacc[8][4];
#pragma unroll
    for (int j = 0; j < 8; ++j)
#pragma unroll
        for (int q = 0; q < 4; ++q) oacc[j][q] = 0.f;
    float mrow[2] = { -1e30f, -1e30f };
    float lrow[2] = { 0.f, 0.f };

    const int aRow  = wm + (lane & 15);
    const int bRowS = ((lane >> 4) << 3) + (lane & 7);
    const int ntiles = qi + 1;

    uint32_t aQh[4][4], aQl[4][4];                   // Q frags, hoisted

    fillQ();
    fillKV(0, 0);
    CP_COMMIT();

    for (int kt = 0; kt < ntiles; ++kt) {
        const int kb = kt << 7;
        const uint32_t sKh = sb + 32768 + (kt & 1) * 65536;
        const uint32_t sKl = sKh + 16384, sVh = sKh + 32768, sVl = sKh + 49152;

        if (kt + 1 < ntiles) {
            fillKV(kt + 1, (kt + 1) & 1);
            CP_COMMIT();
            CP_WAIT1();
        } else {
            CP_WAIT0();
        }
        __syncthreads();

        if (kt == 0) {
#pragma unroll
            for (int k16 = 0; k16 < 4; ++k16) {
                const int kbA = k16 * 32 + ((lane >> 4) & 1) * 16;
                const uint32_t offA = SWZ128(aRow * 128 + kbA);
                ldsm4(aQh[k16], sQh + offA);
                ldsm4(aQl[k16], sQl + offA);
            }
        }

        // ---- S = Q K^T (split, fp32 accum), 16 rows x 128 keys per warp ----
        float sacc[16][4];
#pragma unroll
        for (int j = 0; j < 16; ++j)
#pragma unroll
            for (int q = 0; q < 4; ++q) sacc[j][q] = 0.f;

#pragma unroll
        for (int k16 = 0; k16 < 4; ++k16) {
            const int kbB = k16 * 32 + ((lane >> 3) & 1) * 16;
            uint32_t bH[2][4], bL[2][4];
            {
                const uint32_t off = SWZ128(bRowS * 128 + kbB);
                ldsm4(bH[0], sKh + off);
                ldsm4(bL[0], sKl + off);
            }
#pragma unroll
            for (int ni = 0; ni < 8; ++ni) {
                const int cur = ni & 1;
                if (ni < 7) {
                    const uint32_t off = SWZ128((bRowS + (ni + 1) * 16) * 128 + kbB);
                    ldsm4(bH[cur ^ 1], sKh + off);
                    ldsm4(bL[cur ^ 1], sKl + off);
                }
#pragma unroll
                for (int h2 = 0; h2 < 2; ++h2) {
                    float* d = sacc[ni * 2 + h2];
                    mma_bf16(d, aQh[k16], &bH[cur][h2 * 2]);
                    mma_bf16(d, aQh[k16], &bL[cur][h2 * 2]);
                    mma_bf16(d, aQl[k16], &bH[cur][h2 * 2]);
                }
            }
        }

        // ---- causal mask (exactly one diagonal tile: kt == qi) ----
        if (kt == qi) {
            const int row0 = qbase + wm + g;
#pragma unroll
            for (int j = 0; j < 16; ++j) {
                const int col = kb + j * 8 + tq * 2;
                if (col     > row0)     sacc[j][0] = -1e30f;
                if (col + 1 > row0)     sacc[j][1] = -1e30f;
                if (col     > row0 + 8) sacc[j][2] = -1e30f;
                if (col + 1 > row0 + 8) sacc[j][3] = -1e30f;
            }
        }

        // ---- online softmax (2 rows/thread, quad reductions) ----
#pragma unroll
        for (int rr = 0; rr < 2; ++rr) {
            const int i0 = rr * 2;
            float mt = -1e30f;
#pragma unroll
            for (int j = 0; j < 16; ++j)
                mt = fmaxf(mt, fmaxf(sacc[j][i0], sacc[j][i0 + 1]));
            mt = fmaxf(mt, __shfl_xor_sync(0xffffffffu, mt, 1));
            mt = fmaxf(mt, __shfl_xor_sync(0xffffffffu, mt, 2));
            const float mn = fmaxf(mrow[rr], mt);
            const float alpha = __expf(mrow[rr] - mn);
            mrow[rr] = mn;
            float ps = 0.f;
#pragma unroll
            for (int j = 0; j < 16; ++j) {
                const float p0 = __expf(sacc[j][i0] - mn);
                const float p1 = __expf(sacc[j][i0 + 1] - mn);
                sacc[j][i0] = p0; sacc[j][i0 + 1] = p1;
                ps += p0 + p1;
            }
            ps += __shfl_xor_sync(0xffffffffu, ps, 1);
            ps += __shfl_xor_sync(0xffffffffu, ps, 2);
            lrow[rr] = lrow[rr] * alpha + ps;
#pragma unroll
            for (int j = 0; j < 8; ++j) {
                oacc[j][i0] *= alpha;
                oacc[j][i0 + 1] *= alpha;
            }
        }

        // ---- O += P V (P split register-direct; V via ldmatrix.trans) ----
#pragma unroll
        for (int kk = 0; kk < 8; ++kk) {
            const float* s0 = sacc[2 * kk];
            const float* s1 = sacc[2 * kk + 1];
            uint32_t aPh[4], aPl[4];
            {
                float h00 = __bfloat162float(__float2bfloat16(s0[0]));
                float h01 = __bfloat162float(__float2bfloat16(s0[1]));
                float h02 = __bfloat162float(__float2bfloat16(s0[2]));
                float h03 = __bfloat162float(__float2bfloat16(s0[3]));
                float h10 = __bfloat162float(__float2bfloat16(s1[0]));
                float h11 = __bfloat162float(__float2bfloat16(s1[1]));
                float h12 = __bfloat162float(__float2bfloat16(s1[2]));
                float h13 = __bfloat162float(__float2bfloat16(s1[3]));
                aPh[0] = pack_bf16(s0[0], s0[1]);
                aPh[1] = pack_bf16(s0[2], s0[3]);
                aPh[2] = pack_bf16(s1[0], s1[1]);
                aPh[3] = pack_bf16(s1[2], s1[3]);
                aPl[0] = pack_bf16(s0[0] - h00, s0[1] - h01);
                aPl[1] = pack_bf16(s0[2] - h02, s0[3] - h03);
                aPl[2] = pack_bf16(s1[0] - h10, s1[1] - h11);
                aPl[3] = pack_bf16(s1[2] - h12, s1[3] - h13);
            }
            const int vr = kk * 16 + (lane & 15);
            const int vc = ((lane >> 4) & 1) * 16;
            uint32_t vH[4][4], vL[4][4];
#pragma unroll
            for (int ni = 0; ni < 4; ++ni) {
                const uint32_t off = SWZ128(vr * 128 + ni * 32 + vc);
                ldsm4t(vH[ni], sVh + off);
                ldsm4t(vL[ni], sVl + off);
            }
#pragma unroll
            for (int ni = 0; ni < 4; ++ni)
#pragma unroll
                for (int h2 = 0; h2 < 2; ++h2) {
                    float* d = oacc[ni * 2 + h2];
                    mma_bf16(d, aPh, &vH[ni][h2 * 2]);
                    mma_bf16(d, aPh, &vL[ni][h2 * 2]);
                    mma_bf16(d, aPl, &vH[ni][h2 * 2]);
                }
        }
        __syncthreads();
    }

    // ---- epilogue: normalize, split hi/lo, store (K-major [M][1024]) ----
    const float inv0 = 1.f / lrow[0];
    const float inv1 = 1.f / lrow[1];
    const int row0 = qbase + wm + g;
#pragma unroll
    for (int j = 0; j < 8; ++j) {
        const int col = hcol + j * 8 + tq * 2;
        const float v0 = oacc[j][0] * inv0, v1 = oacc[j][1] * inv0;
        const float v2 = oacc[j][2] * inv1, v3 = oacc[j][3] * inv1;
        const float e0 = __bfloat162float(__float2bfloat16(v0));
        const float e1 = __bfloat162float(__float2bfloat16(v1));
        const float e2 = __bfloat162float(__float2bfloat16(v2));
        const float e3 = __bfloat162float(__float2bfloat16(v3));
        const size_t o0 = (brow + row0) * C_DIM + col;
        const size_t o1 = (brow + row0 + 8) * C_DIM + col;
        *(uint32_t*)&ohi[o0] = pack_bf16(v0, v1);
        *(uint32_t*)&olo[o0] = pack_bf16(v0 - e0, v1 - e1);
        *(uint32_t*)&ohi[o1] = pack_bf16(v2, v3);
        *(uint32_t*)&olo[o1] = pack_bf16(v2 - e2, v3 - e3);
    }
}

// ---------------------------------------------------------------------------
extern "C" void kernel_launch(void* const* d_in, const int* in_sizes, int n_in,
                              void* d_out, int out_size)
{
    const float* x      = (const float*)d_in[0];
    const float* qkv_w  = (const float*)d_in[1];
    const float* qkv_b  = (const float*)d_in[2];
    const float* out_w  = (const float*)d_in[3];
    const float* out_b  = (const float*)d_in[4];
    float* out = (float*)d_out;

    __nv_bfloat16 *qvh, *qvl, *xhi, *xlo, *ahi, *alo, *wqh, *wql, *woh, *wol;
    cudaGetSymbolAddress((void**)&qvh, g_qkvh);
    cudaGetSymbolAddress((void**)&qvl, g_qkvl);
    cudaGetSymbolAddress((void**)&xhi, g_xhi);
    cudaGetSymbolAddress((void**)&xlo, g_xlo);
    cudaGetSymbolAddress((void**)&ahi, g_ahi);
    cudaGetSymbolAddress((void**)&alo, g_alo);
    cudaGetSymbolAddress((void**)&wqh, g_wqt_hi);
    cudaGetSymbolAddress((void**)&wql, g_wqt_lo);
    cudaGetSymbolAddress((void**)&woh, g_wot_hi);
    cudaGetSymbolAddress((void**)&wol, g_wot_lo);

    cudaFuncSetAttribute(gemm_mma, cudaFuncAttributeMaxDynamicSharedMemorySize, SMEM_GEMM);
    cudaFuncSetAttribute(attn_mma, cudaFuncAttributeMaxDynamicSharedMemorySize, SMEM_ATT2);

    // Prepasses: split x; transpose+split weights
    split_k<<<(MTOT * C_DIM / 4 + 255) / 256, 256>>>(x, xhi, xlo, MTOT * C_DIM / 4);
    tsplit_k<<<dim3(C3 / 32, C_DIM / 32), dim3(32, 8)>>>(qkv_w, wqh, wql, C_DIM, C3);
    tsplit_k<<<dim3(C_DIM / 32, C_DIM / 32), dim3(32, 8)>>>(out_w, woh, wol, C_DIM, C_DIM);

    // 1) QKV projection -> split bf16 output (static persistent)
    gemm_mma<<<148, 256, SMEM_GEMM>>>(
        xhi, xlo, wqh, wql, qkv_b, nullptr, qvh, qvl, C3, 1,
        C3 / 128, (C3 / 128) * (MTOT / 256));

    // 2) Causal MHA (128-key tiles, all-bf16 data path, double-buffered)
    attn_mma<<<dim3(TT / 128, BB * HH), 256, SMEM_ATT2>>>(qvh, qvl, ahi, alo);

    // 3) Output projection -> fp32 final output (static persistent)
    gemm_mma<<<148, 256, SMEM_GEMM>>>(
        ahi, alo, woh, wol, out_b, out, nullptr, nullptr, C_DIM, 0,
        C_DIM / 128, (C_DIM / 128) * (MTOT / 256));
}